// round 1
// baseline (speedup 1.0000x reference)
#include <cuda_runtime.h>
#include <math.h>

#define DIM   128
#define HEADS 4
#define HD    32
#define NTOK  128
#define BWIN  2048
#define NMASK 256
#define SCALEF 0.1767766952966369f   // 32^-0.5

// ---------------- device scratch (no runtime allocation allowed) ----------------
__device__ float g_cmask[NMASK * NTOK * NTOK];                  // 16 MB  (mask + sp_mask, index b%256)
__device__ float g_rpb[HEADS * NTOK * NTOK];                    // 256 KB (gathered rel-pos bias)
__device__ float g_q[(size_t)BWIN * HEADS * NTOK * HD];         // 128 MB
__device__ float g_k[(size_t)BWIN * HEADS * NTOK * HD];         // 128 MB
__device__ float g_v[(size_t)BWIN * HEADS * NTOK * HD];         // 128 MB
__device__ float g_ctx[(size_t)BWIN * NTOK * DIM];              // 128 MB

// ---------------- prep kernels ----------------
__global__ void prep_cmask_kernel(const float* __restrict__ mask,
                                  const float* __restrict__ sp_mask) {
    int i = (blockIdx.x * 256 + threadIdx.x) * 4;   // 4096 blocks cover 4,194,304 elems
    float4 a = *(const float4*)(mask + i);
    float4 b = *(const float4*)(sp_mask + i);
    float4 o;
    o.x = a.x + b.x; o.y = a.y + b.y; o.z = a.z + b.z; o.w = a.w + b.w;
    *(float4*)(g_cmask + i) = o;
}

__global__ void prep_rpb_kernel(const int* __restrict__ rpi,
                                const float* __restrict__ bias_table) {
    int i = blockIdx.x * 256 + threadIdx.x;          // 64 blocks * 256 = 16384
    int t = rpi[i];
#pragma unroll
    for (int h = 0; h < HEADS; ++h)
        g_rpb[h * NTOK * NTOK + i] = bias_table[t * HEADS + h];
}

// ---------------- QKV projection: per (window b, s in {q,k,v}) ----------------
// out[t][o] = sum_c x[b][t][c] * w_qkv[s*128+o][c] + b_qkv[s*128+o]   (q scaled)
// smem: xsT[64][128] (K-chunk transposed), wsT[64][128]  -> 64 KB, 2 CTAs/SM
__global__ __launch_bounds__(256, 2)
void qkv_kernel(const float* __restrict__ x,
                const float* __restrict__ w_qkv,
                const float* __restrict__ b_qkv) {
    int b = blockIdx.x;
    int s = blockIdx.y;                  // 0=q, 1=k, 2=v
    extern __shared__ float sm[];
    float* xsT = sm;                     // [cc][t]  cc in chunk of 64
    float* wsT = sm + 64 * NTOK;         // [cc][o]

    const float* xb = x + (size_t)b * NTOK * DIM;
    const float* wb = w_qkv + s * DIM * DIM;

    int tid = threadIdx.x;
    int ty = tid >> 4, tx = tid & 15;
    int r0 = ty * 8, c0 = tx * 8;

    float acc[8][8];
#pragma unroll
    for (int i = 0; i < 8; ++i)
#pragma unroll
        for (int j = 0; j < 8; ++j) acc[i][j] = 0.f;

    for (int cb = 0; cb < DIM; cb += 64) {
        __syncthreads();
        // load x chunk transposed: xsT[cc][t] = x[t][cb+cc]
        for (int i2 = tid * 4; i2 < NTOK * 64; i2 += 256 * 4) {
            int t = i2 >> 6, cc = i2 & 63;
            float4 v = *(const float4*)(xb + t * DIM + cb + cc);
            xsT[(cc + 0) * NTOK + t] = v.x;
            xsT[(cc + 1) * NTOK + t] = v.y;
            xsT[(cc + 2) * NTOK + t] = v.z;
            xsT[(cc + 3) * NTOK + t] = v.w;
        }
        // load w chunk transposed: wsT[cc][o] = w[o][cb+cc]
        for (int i2 = tid * 4; i2 < DIM * 64; i2 += 256 * 4) {
            int o = i2 >> 6, cc = i2 & 63;
            float4 v = *(const float4*)(wb + o * DIM + cb + cc);
            wsT[(cc + 0) * DIM + o] = v.x;
            wsT[(cc + 1) * DIM + o] = v.y;
            wsT[(cc + 2) * DIM + o] = v.z;
            wsT[(cc + 3) * DIM + o] = v.w;
        }
        __syncthreads();
#pragma unroll 4
        for (int c = 0; c < 64; ++c) {
            float a[8], w8[8];
            *(float4*)(a)     = *(const float4*)(xsT + c * NTOK + r0);
            *(float4*)(a + 4) = *(const float4*)(xsT + c * NTOK + r0 + 4);
            *(float4*)(w8)     = *(const float4*)(wsT + c * DIM + c0);
            *(float4*)(w8 + 4) = *(const float4*)(wsT + c * DIM + c0 + 4);
#pragma unroll
            for (int i = 0; i < 8; ++i)
#pragma unroll
                for (int j = 0; j < 8; ++j)
                    acc[i][j] = fmaf(a[i], w8[j], acc[i][j]);
        }
    }

    float scale = (s == 0) ? SCALEF : 1.0f;
    float* gout = (s == 0) ? g_q : (s == 1) ? g_k : g_v;
#pragma unroll
    for (int i = 0; i < 8; ++i) {
        int t = r0 + i;
#pragma unroll
        for (int j0 = 0; j0 < 8; j0 += 4) {
            int o = c0 + j0;
            int hh = o >> 5, d = o & 31;
            float4 v;
            v.x = (acc[i][j0 + 0] + b_qkv[s * DIM + o + 0]) * scale;
            v.y = (acc[i][j0 + 1] + b_qkv[s * DIM + o + 1]) * scale;
            v.z = (acc[i][j0 + 2] + b_qkv[s * DIM + o + 2]) * scale;
            v.w = (acc[i][j0 + 3] + b_qkv[s * DIM + o + 3]) * scale;
            *(float4*)(gout + (((size_t)b * HEADS + hh) * NTOK + t) * HD + d) = v;
        }
    }
}

// ---------------- attention: per (window b, head h) ----------------
// S = q k^T + cmask[b%256] + rpb[h]; softmax rows; ctx_h = P v
// smem: qsT[32][128], ksT[32][128], vs[128][32], P[128][129]  = 115200 B, 2 CTAs/SM
__global__ __launch_bounds__(256, 2)
void att_kernel() {
    int b = blockIdx.x, h = blockIdx.y;
    extern __shared__ float sm[];
    float* qsT = sm;                      // [d][t]
    float* ksT = sm + 32 * NTOK;          // [d][t]
    float* vs  = sm + 2 * 32 * NTOK;      // [t][d]
    float* P   = sm + 3 * 32 * NTOK;      // [r][j], stride 129

    int tid = threadIdx.x;
    const float* gq = g_q + ((size_t)b * HEADS + h) * NTOK * HD;
    const float* gk = g_k + ((size_t)b * HEADS + h) * NTOK * HD;
    const float* gv = g_v + ((size_t)b * HEADS + h) * NTOK * HD;

    // load q,k transposed; v natural
    for (int i = tid * 4; i < NTOK * HD; i += 256 * 4) {
        int t = i >> 5, d = i & 31;
        float4 a = *(const float4*)(gq + i);
        qsT[(d + 0) * NTOK + t] = a.x;
        qsT[(d + 1) * NTOK + t] = a.y;
        qsT[(d + 2) * NTOK + t] = a.z;
        qsT[(d + 3) * NTOK + t] = a.w;
        float4 kk = *(const float4*)(gk + i);
        ksT[(d + 0) * NTOK + t] = kk.x;
        ksT[(d + 1) * NTOK + t] = kk.y;
        ksT[(d + 2) * NTOK + t] = kk.z;
        ksT[(d + 3) * NTOK + t] = kk.w;
        *(float4*)(vs + i) = *(const float4*)(gv + i);
    }
    __syncthreads();

    int ty = tid >> 4, tx = tid & 15;
    int r0 = ty * 8, c0 = tx * 8;

    float acc[8][8];
#pragma unroll
    for (int i = 0; i < 8; ++i)
#pragma unroll
        for (int j = 0; j < 8; ++j) acc[i][j] = 0.f;

#pragma unroll 8
    for (int d = 0; d < HD; ++d) {
        float a[8], kk[8];
        *(float4*)(a)      = *(const float4*)(qsT + d * NTOK + r0);
        *(float4*)(a + 4)  = *(const float4*)(qsT + d * NTOK + r0 + 4);
        *(float4*)(kk)     = *(const float4*)(ksT + d * NTOK + c0);
        *(float4*)(kk + 4) = *(const float4*)(ksT + d * NTOK + c0 + 4);
#pragma unroll
        for (int i = 0; i < 8; ++i)
#pragma unroll
            for (int j = 0; j < 8; ++j)
                acc[i][j] = fmaf(a[i], kk[j], acc[i][j]);
    }

    // additive biases (L2-resident)
    const float* cm = g_cmask + (size_t)(b & (NMASK - 1)) * NTOK * NTOK;
    const float* rp = g_rpb + (size_t)h * NTOK * NTOK;
#pragma unroll
    for (int i = 0; i < 8; ++i) {
        const float* cmr = cm + (r0 + i) * NTOK + c0;
        const float* rpr = rp + (r0 + i) * NTOK + c0;
        float4 m0 = *(const float4*)(cmr);
        float4 m1 = *(const float4*)(cmr + 4);
        float4 p0 = *(const float4*)(rpr);
        float4 p1 = *(const float4*)(rpr + 4);
        acc[i][0] += m0.x + p0.x;  acc[i][1] += m0.y + p0.y;
        acc[i][2] += m0.z + p0.z;  acc[i][3] += m0.w + p0.w;
        acc[i][4] += m1.x + p1.x;  acc[i][5] += m1.y + p1.y;
        acc[i][6] += m1.z + p1.z;  acc[i][7] += m1.w + p1.w;
    }

    // softmax: each row split across 16 tx-lanes (contiguous 16-lane groups)
#pragma unroll
    for (int i = 0; i < 8; ++i) {
        float mx = acc[i][0];
#pragma unroll
        for (int j = 1; j < 8; ++j) mx = fmaxf(mx, acc[i][j]);
#pragma unroll
        for (int o = 8; o > 0; o >>= 1)
            mx = fmaxf(mx, __shfl_xor_sync(0xffffffffu, mx, o));
        float ssum = 0.f;
#pragma unroll
        for (int j = 0; j < 8; ++j) {
            acc[i][j] = __expf(acc[i][j] - mx);
            ssum += acc[i][j];
        }
#pragma unroll
        for (int o = 8; o > 0; o >>= 1)
            ssum += __shfl_xor_sync(0xffffffffu, ssum, o);
        float inv = 1.0f / ssum;
#pragma unroll
        for (int j = 0; j < 8; ++j)
            P[(r0 + i) * 129 + c0 + j] = acc[i][j] * inv;
    }
    __syncthreads();

    // PV: thread pair per row; 16 output channels each
    int r = tid >> 1;
    int d0 = (tid & 1) * 16;
    float out[16];
#pragma unroll
    for (int q = 0; q < 16; ++q) out[q] = 0.f;
    const float* Pr = P + r * 129;
#pragma unroll 4
    for (int j = 0; j < NTOK; ++j) {
        float pv = Pr[j];
        const float* vr = vs + j * HD + d0;
        float4 v0 = *(const float4*)(vr);
        float4 v1 = *(const float4*)(vr + 4);
        float4 v2 = *(const float4*)(vr + 8);
        float4 v3 = *(const float4*)(vr + 12);
        out[0]  = fmaf(pv, v0.x, out[0]);   out[1]  = fmaf(pv, v0.y, out[1]);
        out[2]  = fmaf(pv, v0.z, out[2]);   out[3]  = fmaf(pv, v0.w, out[3]);
        out[4]  = fmaf(pv, v1.x, out[4]);   out[5]  = fmaf(pv, v1.y, out[5]);
        out[6]  = fmaf(pv, v1.z, out[6]);   out[7]  = fmaf(pv, v1.w, out[7]);
        out[8]  = fmaf(pv, v2.x, out[8]);   out[9]  = fmaf(pv, v2.y, out[9]);
        out[10] = fmaf(pv, v2.z, out[10]);  out[11] = fmaf(pv, v2.w, out[11]);
        out[12] = fmaf(pv, v3.x, out[12]);  out[13] = fmaf(pv, v3.y, out[13]);
        out[14] = fmaf(pv, v3.z, out[14]);  out[15] = fmaf(pv, v3.w, out[15]);
    }
    float* go = g_ctx + ((size_t)b * NTOK + r) * DIM + h * HD + d0;
    *(float4*)(go)      = make_float4(out[0], out[1], out[2], out[3]);
    *(float4*)(go + 4)  = make_float4(out[4], out[5], out[6], out[7]);
    *(float4*)(go + 8)  = make_float4(out[8], out[9], out[10], out[11]);
    *(float4*)(go + 12) = make_float4(out[12], out[13], out[14], out[15]);
}

// ---------------- output projection: out = ctx @ w_proj^T + b_proj ----------------
__global__ __launch_bounds__(256, 2)
void proj_kernel(const float* __restrict__ w_proj,
                 const float* __restrict__ b_proj,
                 float* __restrict__ out) {
    int b = blockIdx.x;
    extern __shared__ float sm[];
    float* xsT = sm;                     // [cc][t]
    float* wsT = sm + 64 * NTOK;         // [cc][j]

    const float* xb = g_ctx + (size_t)b * NTOK * DIM;

    int tid = threadIdx.x;
    int ty = tid >> 4, tx = tid & 15;
    int r0 = ty * 8, c0 = tx * 8;

    float acc[8][8];
#pragma unroll
    for (int i = 0; i < 8; ++i)
#pragma unroll
        for (int j = 0; j < 8; ++j) acc[i][j] = 0.f;

    for (int cb = 0; cb < DIM; cb += 64) {
        __syncthreads();
        for (int i2 = tid * 4; i2 < NTOK * 64; i2 += 256 * 4) {
            int t = i2 >> 6, cc = i2 & 63;
            float4 v = *(const float4*)(xb + t * DIM + cb + cc);
            xsT[(cc + 0) * NTOK + t] = v.x;
            xsT[(cc + 1) * NTOK + t] = v.y;
            xsT[(cc + 2) * NTOK + t] = v.z;
            xsT[(cc + 3) * NTOK + t] = v.w;
        }
        for (int i2 = tid * 4; i2 < DIM * 64; i2 += 256 * 4) {
            int o = i2 >> 6, cc = i2 & 63;
            float4 v = *(const float4*)(w_proj + o * DIM + cb + cc);
            wsT[(cc + 0) * DIM + o] = v.x;
            wsT[(cc + 1) * DIM + o] = v.y;
            wsT[(cc + 2) * DIM + o] = v.z;
            wsT[(cc + 3) * DIM + o] = v.w;
        }
        __syncthreads();
#pragma unroll 4
        for (int c = 0; c < 64; ++c) {
            float a[8], w8[8];
            *(float4*)(a)     = *(const float4*)(xsT + c * NTOK + r0);
            *(float4*)(a + 4) = *(const float4*)(xsT + c * NTOK + r0 + 4);
            *(float4*)(w8)     = *(const float4*)(wsT + c * DIM + c0);
            *(float4*)(w8 + 4) = *(const float4*)(wsT + c * DIM + c0 + 4);
#pragma unroll
            for (int i = 0; i < 8; ++i)
#pragma unroll
                for (int j = 0; j < 8; ++j)
                    acc[i][j] = fmaf(a[i], w8[j], acc[i][j]);
        }
    }

#pragma unroll
    for (int i = 0; i < 8; ++i) {
        int t = r0 + i;
#pragma unroll
        for (int j0 = 0; j0 < 8; j0 += 4) {
            int o = c0 + j0;
            float4 v;
            v.x = acc[i][j0 + 0] + b_proj[o + 0];
            v.y = acc[i][j0 + 1] + b_proj[o + 1];
            v.z = acc[i][j0 + 2] + b_proj[o + 2];
            v.w = acc[i][j0 + 3] + b_proj[o + 3];
            *(float4*)(out + ((size_t)b * NTOK + t) * DIM + o) = v;
        }
    }
}

// ---------------- launch ----------------
extern "C" void kernel_launch(void* const* d_in, const int* in_sizes, int n_in,
                              void* d_out, int out_size) {
    const float* x          = (const float*)d_in[0];
    const int*   rpi        = (const int*)d_in[1];
    const float* mask       = (const float*)d_in[2];
    const float* sp_mask    = (const float*)d_in[3];
    const float* w_qkv      = (const float*)d_in[4];
    const float* b_qkv      = (const float*)d_in[5];
    const float* bias_table = (const float*)d_in[6];
    const float* w_proj     = (const float*)d_in[7];
    const float* b_proj     = (const float*)d_in[8];
    float* out = (float*)d_out;

    const int QKV_SMEM  = 64 * 128 * 4 * 2;                     // 65536
    const int ATT_SMEM  = (3 * 32 * 128 + 128 * 129) * 4;       // 115200
    const int PROJ_SMEM = QKV_SMEM;

    cudaFuncSetAttribute((const void*)qkv_kernel,
                         cudaFuncAttributeMaxDynamicSharedMemorySize, QKV_SMEM);
    cudaFuncSetAttribute((const void*)att_kernel,
                         cudaFuncAttributeMaxDynamicSharedMemorySize, ATT_SMEM);
    cudaFuncSetAttribute((const void*)proj_kernel,
                         cudaFuncAttributeMaxDynamicSharedMemorySize, PROJ_SMEM);

    prep_cmask_kernel<<<4096, 256>>>(mask, sp_mask);
    prep_rpb_kernel<<<64, 256>>>(rpi, bias_table);
    qkv_kernel<<<dim3(BWIN, 3), 256, QKV_SMEM>>>(x, w_qkv, b_qkv);
    att_kernel<<<dim3(BWIN, HEADS), 256, ATT_SMEM>>>();
    proj_kernel<<<BWIN, 256, PROJ_SMEM>>>(w_proj, b_proj, out);
}